// round 6
// baseline (speedup 1.0000x reference)
#include <cuda_runtime.h>
#include <cuda_bf16.h>
#include <math.h>

// ---------------------------------------------------------------------------
// BitNetV3 MLP: out = BitLinear(silu(BitLinear(x,Wg)) * BitLinear(x,Wu), Wd)
// BitLinear(x,W): xq = int8-quant(FWHT(x)) ; wq = ternary-quant(W) ; xq @ wq^T
// Shapes: x [2,2048,2048] -> T=4096 tokens, H=2048, I=8192.
// Strategy: exact-integer dp4a GEMMs + per-token/per-matrix dequant scales.
// ---------------------------------------------------------------------------

#define T_TOK 4096
#define H_DIM 2048
#define I_DIM 8192
#define KP1   (H_DIM / 4)   // 512  packed int32 per token (GEMM 1)
#define KP2   (I_DIM / 4)   // 2048 packed int32 per token (GEMM 2)

// FWHT normalization constants (match np.sqrt exactly in double, then float)
#define NORM_2048 0.022097086912079608f   // 1/sqrt(2048)
#define NORM_8192 0.011048543456039804f   // 1/sqrt(8192)

// ------------------------- scratch (allocation-free) -----------------------
__device__ __align__(16) int    g_qx1[T_TOK * KP1];          //   8 MB
__device__ __align__(16) int    g_qx2[T_TOK * KP2];          //  32 MB
__device__ float  g_as1[T_TOK];
__device__ float  g_as2[T_TOK];
__device__ __align__(16) int    g_qwg[I_DIM * KP1];          //  16 MB
__device__ __align__(16) int    g_qwu[I_DIM * KP1];          //  16 MB
__device__ __align__(16) int    g_qwd[H_DIM * KP2];          //  16 MB
__device__ float  g_ws[4];                                   // weight scales
__device__ double g_part[1024];                              // reduce scratch
__device__ float  g_gate[T_TOK * (size_t)I_DIM];             // 128 MB (gate, then h)

// ------------------------- weight scale = mean(|w|) ------------------------
__global__ void abs_sum_partial(const float* __restrict__ w, long long n,
                                double* __restrict__ part) {
    __shared__ double red[256];
    double s = 0.0;
    for (long long i = (long long)blockIdx.x * 256 + threadIdx.x; i < n;
         i += (long long)gridDim.x * 256)
        s += (double)fabsf(w[i]);
    red[threadIdx.x] = s;
    __syncthreads();
    for (int off = 128; off > 0; off >>= 1) {
        if ((int)threadIdx.x < off) red[threadIdx.x] += red[threadIdx.x + off];
        __syncthreads();
    }
    if (threadIdx.x == 0) part[blockIdx.x] = red[0];
}

__global__ void abs_sum_final(const double* __restrict__ part, int np,
                              long long n, float* __restrict__ outScale) {
    __shared__ double red[256];
    double s = 0.0;
    for (int i = threadIdx.x; i < np; i += 256) s += part[i];
    red[threadIdx.x] = s;
    __syncthreads();
    for (int off = 128; off > 0; off >>= 1) {
        if ((int)threadIdx.x < off) red[threadIdx.x] += red[threadIdx.x + off];
        __syncthreads();
    }
    if (threadIdx.x == 0)
        outScale[0] = fmaxf((float)(red[0] / (double)n), 1e-5f);
}

// ------------------- ternary weight quantize + int8 pack -------------------
__global__ void quant_pack_w(const float* __restrict__ w,
                             const float* __restrict__ sc,
                             int* __restrict__ q, int n4) {
    int i = blockIdx.x * blockDim.x + threadIdx.x;
    if (i >= n4) return;
    float s = sc[0];
    float4 v = reinterpret_cast<const float4*>(w)[i];
    int q0 = (int)fminf(fmaxf(rintf(v.x / s), -1.f), 1.f);
    int q1 = (int)fminf(fmaxf(rintf(v.y / s), -1.f), 1.f);
    int q2 = (int)fminf(fmaxf(rintf(v.z / s), -1.f), 1.f);
    int q3 = (int)fminf(fmaxf(rintf(v.w / s), -1.f), 1.f);
    q[i] = (q0 & 0xFF) | ((q1 & 0xFF) << 8) | ((q2 & 0xFF) << 16)
         | ((q3 & 0xFF) << 24);
}

// --------------- FWHT (last axis) + per-token int8 quant + pack ------------
// Pairing identical to reference: stage h pairs (i, i+h) within 2h blocks,
// h = 1,2,...,N/2; normalize by 1/sqrt(N) after all stages.
template <int N, int TPB>
__global__ void fwht_quant(const float* __restrict__ X, int* __restrict__ Q,
                           float* __restrict__ scales, float norm) {
    __shared__ float s[N];
    __shared__ float red[TPB];
    const int t = blockIdx.x;
    const float* x = X + (size_t)t * N;

    for (int i = threadIdx.x; i < N; i += TPB) s[i] = x[i];
    __syncthreads();

    for (int h = 1; h < N; h <<= 1) {
        for (int p = threadIdx.x; p < N / 2; p += TPB) {
            int i = ((p & ~(h - 1)) << 1) | (p & (h - 1));
            float a = s[i], b = s[i + h];
            s[i] = a + b;
            s[i + h] = a - b;
        }
        __syncthreads();
    }

    // absmax of normalized transform
    float m = 0.f;
    for (int i = threadIdx.x; i < N; i += TPB)
        m = fmaxf(m, fabsf(s[i] * norm));
    red[threadIdx.x] = m;
    __syncthreads();
    for (int off = TPB / 2; off > 0; off >>= 1) {
        if ((int)threadIdx.x < off)
            red[threadIdx.x] = fmaxf(red[threadIdx.x], red[threadIdx.x + off]);
        __syncthreads();
    }
    float scale = 127.f / fmaxf(red[0], 1e-5f);
    if (threadIdx.x == 0) scales[t] = scale;

    // quantize + pack 4 int8 per int32
    for (int i = threadIdx.x; i < N / 4; i += TPB) {
        float v0 = s[4 * i + 0] * norm * scale;
        float v1 = s[4 * i + 1] * norm * scale;
        float v2 = s[4 * i + 2] * norm * scale;
        float v3 = s[4 * i + 3] * norm * scale;
        int q0 = (int)fminf(fmaxf(rintf(v0), -128.f), 127.f);
        int q1 = (int)fminf(fmaxf(rintf(v1), -128.f), 127.f);
        int q2 = (int)fminf(fmaxf(rintf(v2), -128.f), 127.f);
        int q3 = (int)fminf(fmaxf(rintf(v3), -128.f), 127.f);
        Q[(size_t)t * (N / 4) + i] = (q0 & 0xFF) | ((q1 & 0xFF) << 8)
                                   | ((q2 & 0xFF) << 16) | ((q3 & 0xFF) << 24);
    }
}

// ----------------------------- dp4a int8 GEMM ------------------------------
// C[t,o] = (sum_k a8[t,k]*b8[o,k]) * wS / actScale[t]
// MODE 0: write f32.  MODE 1: C holds gate; write silu(gate)*up back into C.
#define BM 128
#define BN 128
#define BKI 16  // 16 int32 = 64 int8 along K per tile

template <int MODE>
__global__ __launch_bounds__(256)
void gemm_dp4a(const int* __restrict__ A,   // [T][Kp]
               const int* __restrict__ B,   // [O][Kp]
               float* __restrict__ C,       // [T][O]
               int O, int Kp,
               const float* __restrict__ actScale,
               const float* __restrict__ wScale) {
    __shared__ __align__(16) int As[BKI][BM];
    __shared__ __align__(16) int Bs[BKI][BN];

    const int tid = threadIdx.x;
    const int tx = tid & 15;       // 0..15 -> N
    const int ty = tid >> 4;       // 0..15 -> M
    const int blockM = blockIdx.y * BM;
    const int blockN = blockIdx.x * BN;

    int acc[8][8];
#pragma unroll
    for (int i = 0; i < 8; i++)
#pragma unroll
        for (int j = 0; j < 8; j++) acc[i][j] = 0;

    const int ldr = tid >> 2;          // 0..63
    const int ldc = (tid & 3) * 4;     // 0,4,8,12

    for (int kt = 0; kt < Kp; kt += BKI) {
#pragma unroll
        for (int rr = 0; rr < 2; rr++) {
            int r = ldr + rr * 64;
            int4 va = *reinterpret_cast<const int4*>(
                &A[(size_t)(blockM + r) * Kp + kt + ldc]);
            As[ldc + 0][r] = va.x; As[ldc + 1][r] = va.y;
            As[ldc + 2][r] = va.z; As[ldc + 3][r] = va.w;
            int4 vb = *reinterpret_cast<const int4*>(
                &B[(size_t)(blockN + r) * Kp + kt + ldc]);
            Bs[ldc + 0][r] = vb.x; Bs[ldc + 1][r] = vb.y;
            Bs[ldc + 2][r] = vb.z; Bs[ldc + 3][r] = vb.w;
        }
        __syncthreads();

#pragma unroll
        for (int kk = 0; kk < BKI; kk++) {
            int4 a0 = *reinterpret_cast<const int4*>(&As[kk][ty * 8]);
            int4 a1 = *reinterpret_cast<const int4*>(&As[kk][ty * 8 + 4]);
            int4 b0 = *reinterpret_cast<const int4*>(&Bs[kk][tx * 8]);
            int4 b1 = *reinterpret_cast<const int4*>(&Bs[kk][tx * 8 + 4]);
            int a[8] = {a0.x, a0.y, a0.z, a0.w, a1.x, a1.y, a1.z, a1.w};
            int b[8] = {b0.x, b0.y, b0.z, b0.w, b1.x, b1.y, b1.z, b1.w};
#pragma unroll
            for (int i = 0; i < 8; i++)
#pragma unroll
                for (int j = 0; j < 8; j++)
                    acc[i][j] = __dp4a(a[i], b[j], acc[i][j]);
        }
        __syncthreads();
    }

    const float wS = wScale[0];
#pragma unroll
    for (int i = 0; i < 8; i++) {
        int m = blockM + ty * 8 + i;
        float f = wS / actScale[m];
#pragma unroll
        for (int j = 0; j < 8; j++) {
            int o = blockN + tx * 8 + j;
            size_t idx = (size_t)m * O + o;
            float v = (float)acc[i][j] * f;
            if (MODE == 0) {
                C[idx] = v;
            } else {
                float g = C[idx];                       // gate
                C[idx] = (g / (1.f + expf(-g))) * v;    // silu(gate)*up
            }
        }
    }
}

// ------------------------------- launcher ----------------------------------
extern "C" void kernel_launch(void* const* d_in, const int* in_sizes, int n_in,
                              void* d_out, int out_size) {
    const float* x  = (const float*)d_in[0];   // [2,2048,2048]
    const float* wg = (const float*)d_in[1];   // [8192,2048]
    const float* wu = (const float*)d_in[2];   // [8192,2048]
    const float* wd = (const float*)d_in[3];   // [2048,8192]
    float* out = (float*)d_out;                // [2,2048,2048]

    void* p;
    cudaGetSymbolAddress(&p, g_qx1);  int*    qx1  = (int*)p;
    cudaGetSymbolAddress(&p, g_qx2);  int*    qx2  = (int*)p;
    cudaGetSymbolAddress(&p, g_as1);  float*  as1  = (float*)p;
    cudaGetSymbolAddress(&p, g_as2);  float*  as2  = (float*)p;
    cudaGetSymbolAddress(&p, g_qwg);  int*    qwg  = (int*)p;
    cudaGetSymbolAddress(&p, g_qwu);  int*    qwu  = (int*)p;
    cudaGetSymbolAddress(&p, g_qwd);  int*    qwd  = (int*)p;
    cudaGetSymbolAddress(&p, g_ws);   float*  ws   = (float*)p;
    cudaGetSymbolAddress(&p, g_part); double* part = (double*)p;
    cudaGetSymbolAddress(&p, g_gate); float*  gate = (float*)p;

    const long long nW1 = (long long)I_DIM * H_DIM;   // 16777216
    const long long nW2 = (long long)H_DIM * I_DIM;   // 16777216

    // weight scales (mean |w|) + ternary pack
    abs_sum_partial<<<1024, 256>>>(wg, nW1, part);
    abs_sum_final<<<1, 256>>>(part, 1024, nW1, ws + 0);
    quant_pack_w<<<(int)(nW1 / 4 + 255) / 256, 256>>>(wg, ws + 0, qwg, (int)(nW1 / 4));

    abs_sum_partial<<<1024, 256>>>(wu, nW1, part);
    abs_sum_final<<<1, 256>>>(part, 1024, nW1, ws + 1);
    quant_pack_w<<<(int)(nW1 / 4 + 255) / 256, 256>>>(wu, ws + 1, qwu, (int)(nW1 / 4));

    abs_sum_partial<<<1024, 256>>>(wd, nW2, part);
    abs_sum_final<<<1, 256>>>(part, 1024, nW2, ws + 2);
    quant_pack_w<<<(int)(nW2 / 4 + 255) / 256, 256>>>(wd, ws + 2, qwd, (int)(nW2 / 4));

    // FWHT(2048) + quant of input activations (shared by gate & up)
    fwht_quant<H_DIM, 256><<<T_TOK, 256>>>(x, qx1, as1, NORM_2048);

    // gate = xq @ Wg^T ; then h = silu(gate) * (xq @ Wu^T) fused in epilogue
    gemm_dp4a<0><<<dim3(I_DIM / BN, T_TOK / BM), 256>>>(
        qx1, qwg, gate, I_DIM, KP1, as1, ws + 0);
    gemm_dp4a<1><<<dim3(I_DIM / BN, T_TOK / BM), 256>>>(
        qx1, qwu, gate, I_DIM, KP1, as1, ws + 1);

    // FWHT(8192) + quant of h
    fwht_quant<I_DIM, 512><<<T_TOK, 512>>>(gate, qx2, as2, NORM_8192);

    // out = hq @ Wd^T
    gemm_dp4a<0><<<dim3(H_DIM / BN, T_TOK / BM), 256>>>(
        qx2, qwd, out, H_DIM, KP2, as2, ws + 2);
}

// round 8
// speedup vs baseline: 1.5785x; 1.5785x over previous
#include <cuda_runtime.h>
#include <cuda_bf16.h>
#include <math.h>
#include <stdint.h>

// ---------------------------------------------------------------------------
// BitNetV3 MLP via IMMA (mma.sync.m16n8k32.s8) tensor cores.
// out = BitLinear(silu(BitLinear(x,Wg)) * BitLinear(x,Wu), Wd)
// BitLinear(x,W): xq = int8-quant(FWHT(x)); wq = ternary int8; s32 GEMM; dequant.
// T=4096 tokens, H=2048, I=8192. All integer math is bit-exact.
// ---------------------------------------------------------------------------

#define T_TOK 4096
#define H_DIM 2048
#define I_DIM 8192

#define NORM_2048 0.022097086912079608f   // 1/sqrt(2048)
#define NORM_8192 0.011048543456039804f   // 1/sqrt(8192)

// ------------------------- scratch (allocation-free) -----------------------
__device__ __align__(16) int    g_qx1[T_TOK * H_DIM / 4];            //  8 MB
__device__ __align__(16) int    g_qx2[T_TOK * I_DIM / 4];            // 32 MB
__device__ float  g_as1[T_TOK];
__device__ float  g_as2[T_TOK];
__device__ __align__(16) int    g_qwg[I_DIM * H_DIM / 4];            // 16 MB
__device__ __align__(16) int    g_qwu[I_DIM * H_DIM / 4];            // 16 MB
__device__ __align__(16) int    g_qwd[H_DIM * I_DIM / 4];            // 16 MB
__device__ float  g_ws[4];
__device__ double g_part[1024];
__device__ float  g_gate[(size_t)T_TOK * I_DIM];                     // 128 MB

// ----------------------------- PTX helpers ---------------------------------
__device__ __forceinline__ uint32_t s2u(const void* p) {
    uint32_t a;
    asm("{ .reg .u64 t; cvta.to.shared.u64 t, %1; cvt.u32.u64 %0, t; }"
        : "=r"(a) : "l"(p));
    return a;
}
__device__ __forceinline__ void cp16(uint32_t d, const void* s) {
    asm volatile("cp.async.cg.shared.global [%0], [%1], 16;" :: "r"(d), "l"(s));
}
__device__ __forceinline__ void cp_commit() { asm volatile("cp.async.commit_group;"); }
__device__ __forceinline__ void cp_wait0()  { asm volatile("cp.async.wait_group 0;"); }
__device__ __forceinline__ void cp_wait1()  { asm volatile("cp.async.wait_group 1;"); }

__device__ __forceinline__ void ldm_x4(uint32_t* r, uint32_t addr) {
    asm volatile("ldmatrix.sync.aligned.m8n8.x4.shared.b16 {%0,%1,%2,%3}, [%4];"
                 : "=r"(r[0]), "=r"(r[1]), "=r"(r[2]), "=r"(r[3]) : "r"(addr));
}
__device__ __forceinline__ void mma_s8(int* d, const uint32_t* a,
                                       uint32_t b0, uint32_t b1) {
    asm volatile(
        "mma.sync.aligned.m16n8k32.row.col.s32.s8.s8.s32 "
        "{%0,%1,%2,%3}, {%4,%5,%6,%7}, {%8,%9}, {%0,%1,%2,%3};"
        : "+r"(d[0]), "+r"(d[1]), "+r"(d[2]), "+r"(d[3])
        : "r"(a[0]), "r"(a[1]), "r"(a[2]), "r"(a[3]), "r"(b0), "r"(b1));
}

// ------------------------- weight scale = mean(|w|) ------------------------
__global__ void abs_sum_partial(const float4* __restrict__ w, int n4,
                                double* __restrict__ part) {
    double s0 = 0, s1 = 0, s2 = 0, s3 = 0;
    for (int i = blockIdx.x * 256 + threadIdx.x; i < n4; i += gridDim.x * 256) {
        float4 v = w[i];
        s0 += (double)fabsf(v.x); s1 += (double)fabsf(v.y);
        s2 += (double)fabsf(v.z); s3 += (double)fabsf(v.w);
    }
    __shared__ double red[256];
    red[threadIdx.x] = (s0 + s1) + (s2 + s3);
    __syncthreads();
    for (int off = 128; off > 0; off >>= 1) {
        if ((int)threadIdx.x < off) red[threadIdx.x] += red[threadIdx.x + off];
        __syncthreads();
    }
    if (threadIdx.x == 0) part[blockIdx.x] = red[0];
}

__global__ void abs_sum_final(const double* __restrict__ part, int np,
                              long long n, float* __restrict__ outScale) {
    __shared__ double red[256];
    double s = 0.0;
    for (int i = threadIdx.x; i < np; i += 256) s += part[i];
    red[threadIdx.x] = s;
    __syncthreads();
    for (int off = 128; off > 0; off >>= 1) {
        if ((int)threadIdx.x < off) red[threadIdx.x] += red[threadIdx.x + off];
        __syncthreads();
    }
    if (threadIdx.x == 0)
        outScale[0] = fmaxf((float)(red[0] / (double)n), 1e-5f);
}

// ------------------- ternary weight quantize + int8 pack -------------------
__global__ void quant_pack_w(const float* __restrict__ w,
                             const float* __restrict__ sc,
                             int* __restrict__ q, int n4) {
    int i = blockIdx.x * blockDim.x + threadIdx.x;
    if (i >= n4) return;
    float s = sc[0];
    float4 v = reinterpret_cast<const float4*>(w)[i];
    int q0 = (int)fminf(fmaxf(rintf(v.x / s), -1.f), 1.f);
    int q1 = (int)fminf(fmaxf(rintf(v.y / s), -1.f), 1.f);
    int q2 = (int)fminf(fmaxf(rintf(v.z / s), -1.f), 1.f);
    int q3 = (int)fminf(fmaxf(rintf(v.w / s), -1.f), 1.f);
    q[i] = (q0 & 0xFF) | ((q1 & 0xFF) << 8) | ((q2 & 0xFF) << 16) | ((q3 & 0xFF) << 24);
}

// --------------- FWHT (last axis) + per-token int8 quant + pack ------------
template <int N, int TPB>
__global__ void fwht_quant(const float* __restrict__ X, int* __restrict__ Q,
                           float* __restrict__ scales, float norm) {
    __shared__ float s[N];
    __shared__ float red[TPB];
    const int t = blockIdx.x;
    const float* x = X + (size_t)t * N;

    for (int i = threadIdx.x; i < N; i += TPB) s[i] = x[i];
    __syncthreads();

    for (int h = 1; h < N; h <<= 1) {
        for (int p = threadIdx.x; p < N / 2; p += TPB) {
            int i = ((p & ~(h - 1)) << 1) | (p & (h - 1));
            float a = s[i], b = s[i + h];
            s[i] = a + b;
            s[i + h] = a - b;
        }
        __syncthreads();
    }

    float m = 0.f;
    for (int i = threadIdx.x; i < N; i += TPB)
        m = fmaxf(m, fabsf(s[i] * norm));
    red[threadIdx.x] = m;
    __syncthreads();
    for (int off = TPB / 2; off > 0; off >>= 1) {
        if ((int)threadIdx.x < off)
            red[threadIdx.x] = fmaxf(red[threadIdx.x], red[threadIdx.x + off]);
        __syncthreads();
    }
    float scale = 127.f / fmaxf(red[0], 1e-5f);
    if (threadIdx.x == 0) scales[t] = scale;

    for (int i = threadIdx.x; i < N / 4; i += TPB) {
        float v0 = s[4 * i + 0] * norm * scale;
        float v1 = s[4 * i + 1] * norm * scale;
        float v2 = s[4 * i + 2] * norm * scale;
        float v3 = s[4 * i + 3] * norm * scale;
        int q0 = (int)fminf(fmaxf(rintf(v0), -128.f), 127.f);
        int q1 = (int)fminf(fmaxf(rintf(v1), -128.f), 127.f);
        int q2 = (int)fminf(fmaxf(rintf(v2), -128.f), 127.f);
        int q3 = (int)fminf(fmaxf(rintf(v3), -128.f), 127.f);
        Q[(size_t)t * (N / 4) + i] = (q0 & 0xFF) | ((q1 & 0xFF) << 8)
                                   | ((q2 & 0xFF) << 16) | ((q3 & 0xFF) << 24);
    }
}

// ---------------------------- IMMA int8 GEMM -------------------------------
// CTA: 128x128 tile, 8 warps (4M x 2N), warp tile 32x64.
// K consumed in 128-byte SW128-swizzled SMEM chunks, double-buffered cp.async.
// C[t,o] = acc * wS / actScale[t]. MODE 1: C holds gate; write silu(gate)*up.
#define GEMM_SMEM (4 * 16384)

template <int MODE>
__global__ __launch_bounds__(256, 2)
void gemm_imma(const char* __restrict__ A,   // [M_total][K] int8 row-major
               const char* __restrict__ Bw,  // [O][K]      int8 row-major
               float* __restrict__ C,        // [M_total][O] f32
               int O, int K,
               const float* __restrict__ actScale,
               const float* __restrict__ wScale) {
    extern __shared__ __align__(1024) char smem[];
    const uint32_t SA0 = s2u(smem);          // A stage 0
    const uint32_t SB0 = SA0 + 16384;        // B stage 0
    const uint32_t SA1 = SB0 + 16384;        // A stage 1
    const uint32_t SB1 = SA1 + 16384;        // B stage 1

    const int tid = threadIdx.x;
    const int lane = tid & 31, w = tid >> 5;
    const int wm = w >> 1, wn = w & 1;       // warp grid 4(M) x 2(N)
    const int blockM = blockIdx.y * 128, blockN = blockIdx.x * 128;

    // ldmatrix lane geometry (SW128: sw(row*128+kb) = row*128 + (kb ^ ((row&7)<<4)))
    const int aRow = wm * 32 + (lane & 7) + ((lane >> 3) & 1) * 8;
    const uint32_t aKh = ((lane >> 4) & 1) * 16;
    const uint32_t aQ  = (uint32_t)(aRow & 7) << 4;
    const int bRow = wn * 64 + (lane & 7) + ((lane >> 4) & 1) * 8;
    const uint32_t bKh = ((lane >> 3) & 1) * 16;
    const uint32_t bQ  = (uint32_t)(bRow & 7) << 4;

    int acc[2][8][4];
#pragma unroll
    for (int i = 0; i < 2; i++)
#pragma unroll
        for (int j = 0; j < 8; j++)
#pragma unroll
            for (int k = 0; k < 4; k++) acc[i][j][k] = 0;

    const char* gA = A  + (size_t)blockM * K;
    const char* gB = Bw + (size_t)blockN * K;
    const int nC = K >> 7;

    // chunk loader: 1024 16B segments per matrix, 256 threads -> 4 each
#define LOAD_CHUNK(dstA, dstB, kt)                                            \
    do {                                                                      \
        _Pragma("unroll")                                                     \
        for (int i = 0; i < 4; i++) {                                         \
            int g = i * 256 + tid;                                            \
            uint32_t off = (uint32_t)g * 16;                                  \
            uint32_t sw = off ^ ((off >> 3) & 0x70);                          \
            int row = g >> 3, cc = (g & 7) * 16;                              \
            cp16((dstA) + sw, gA + (size_t)row * K + (kt) + cc);              \
            cp16((dstB) + sw, gB + (size_t)row * K + (kt) + cc);              \
        }                                                                     \
        cp_commit();                                                          \
    } while (0)

    LOAD_CHUNK(SA0, SB0, 0);

    for (int c = 0; c < nC; c++) {
        const uint32_t cA = (c & 1) ? SA1 : SA0;
        const uint32_t cB = (c & 1) ? SB1 : SB0;
        if (c + 1 < nC) {
            const uint32_t nA = (c & 1) ? SA0 : SA1;
            const uint32_t nB = (c & 1) ? SB0 : SB1;
            LOAD_CHUNK(nA, nB, (c + 1) << 7);
            cp_wait1();
        } else {
            cp_wait0();
        }
        __syncthreads();

        const uint32_t aBase = cA + (uint32_t)aRow * 128;
        const uint32_t bBase = cB + (uint32_t)bRow * 128;
#pragma unroll
        for (int ks = 0; ks < 4; ks++) {
            uint32_t Af[2][4], Bf[4][4];
#pragma unroll
            for (int mr = 0; mr < 2; mr++)
                ldm_x4(Af[mr], aBase + mr * (16 * 128)
                               + (((uint32_t)(ks * 32) + aKh) ^ aQ));
#pragma unroll
            for (int ng = 0; ng < 4; ng++)
                ldm_x4(Bf[ng], bBase + ng * (16 * 128)
                               + (((uint32_t)(ks * 32) + bKh) ^ bQ));
#pragma unroll
            for (int mr = 0; mr < 2; mr++)
#pragma unroll
                for (int nb = 0; nb < 8; nb++)
                    mma_s8(acc[mr][nb], Af[mr],
                           Bf[nb >> 1][(nb & 1) * 2],
                           Bf[nb >> 1][(nb & 1) * 2 + 1]);
        }
        __syncthreads();   // all warps done reading before buffer reuse
    }
#undef LOAD_CHUNK

    // ---------------- epilogue: dequant + store (from registers) -----------
    const float wS = wScale[0];
    const int r = lane >> 2, cq = (lane & 3) * 2;
#pragma unroll
    for (int mr = 0; mr < 2; mr++) {
#pragma unroll
        for (int half = 0; half < 2; half++) {
            const int m = blockM + wm * 32 + mr * 16 + half * 8 + r;
            const float f = wS / __ldg(&actScale[m]);
            float* crow = C + (size_t)m * O + blockN + wn * 64;
#pragma unroll
            for (int nb = 0; nb < 8; nb++) {
                float2 v;
                v.x = (float)acc[mr][nb][half * 2]     * f;
                v.y = (float)acc[mr][nb][half * 2 + 1] * f;
                float* p = crow + nb * 8 + cq;
                if (MODE == 1) {
                    float2 g = *reinterpret_cast<const float2*>(p);
                    v.x *= g.x / (1.f + expf(-g.x));
                    v.y *= g.y / (1.f + expf(-g.y));
                }
                *reinterpret_cast<float2*>(p) = v;
            }
        }
    }
}

// ------------------------------- launcher ----------------------------------
extern "C" void kernel_launch(void* const* d_in, const int* in_sizes, int n_in,
                              void* d_out, int out_size) {
    const float* x  = (const float*)d_in[0];
    const float* wg = (const float*)d_in[1];
    const float* wu = (const float*)d_in[2];
    const float* wd = (const float*)d_in[3];
    float* out = (float*)d_out;

    void* p;
    cudaGetSymbolAddress(&p, g_qx1);  int*    qx1  = (int*)p;
    cudaGetSymbolAddress(&p, g_qx2);  int*    qx2  = (int*)p;
    cudaGetSymbolAddress(&p, g_as1);  float*  as1  = (float*)p;
    cudaGetSymbolAddress(&p, g_as2);  float*  as2  = (float*)p;
    cudaGetSymbolAddress(&p, g_qwg);  int*    qwg  = (int*)p;
    cudaGetSymbolAddress(&p, g_qwu);  int*    qwu  = (int*)p;
    cudaGetSymbolAddress(&p, g_qwd);  int*    qwd  = (int*)p;
    cudaGetSymbolAddress(&p, g_ws);   float*  ws   = (float*)p;
    cudaGetSymbolAddress(&p, g_part); double* part = (double*)p;
    cudaGetSymbolAddress(&p, g_gate); float*  gate = (float*)p;

    cudaFuncSetAttribute(gemm_imma<0>, cudaFuncAttributeMaxDynamicSharedMemorySize, GEMM_SMEM);
    cudaFuncSetAttribute(gemm_imma<1>, cudaFuncAttributeMaxDynamicSharedMemorySize, GEMM_SMEM);

    const long long nW = (long long)I_DIM * H_DIM;
    const int n4 = (int)(nW / 4);

    abs_sum_partial<<<1024, 256>>>((const float4*)wg, n4, part);
    abs_sum_final<<<1, 256>>>(part, 1024, nW, ws + 0);
    quant_pack_w<<<(n4 + 255) / 256, 256>>>(wg, ws + 0, qwg, n4);

    abs_sum_partial<<<1024, 256>>>((const float4*)wu, n4, part);
    abs_sum_final<<<1, 256>>>(part, 1024, nW, ws + 1);
    quant_pack_w<<<(n4 + 255) / 256, 256>>>(wu, ws + 1, qwu, n4);

    abs_sum_partial<<<1024, 256>>>((const float4*)wd, n4, part);
    abs_sum_final<<<1, 256>>>(part, 1024, nW, ws + 2);
    quant_pack_w<<<(n4 + 255) / 256, 256>>>(wd, ws + 2, qwd, n4);

    // FWHT(2048) + int8 quant of input (shared by gate & up)
    fwht_quant<H_DIM, 256><<<T_TOK, 256>>>(x, qx1, as1, NORM_2048);

    // gate = xq @ Wg^T ; then h = silu(gate) * (xq @ Wu^T) fused in epilogue
    gemm_imma<0><<<dim3(I_DIM / 128, T_TOK / 128), 256, GEMM_SMEM>>>(
        (const char*)qx1, (const char*)qwg, gate, I_DIM, H_DIM, as1, ws + 0);
    gemm_imma<1><<<dim3(I_DIM / 128, T_TOK / 128), 256, GEMM_SMEM>>>(
        (const char*)qx1, (const char*)qwu, gate, I_DIM, H_DIM, as1, ws + 1);

    // FWHT(8192) + int8 quant of h
    fwht_quant<I_DIM, 512><<<T_TOK, 512>>>(gate, qx2, as2, NORM_8192);

    // out = hq @ Wd^T
    gemm_imma<0><<<dim3(H_DIM / 128, T_TOK / 128), 256, GEMM_SMEM>>>(
        (const char*)qx2, (const char*)qwd, out, H_DIM, I_DIM, as2, ws + 2);
}

// round 11
// speedup vs baseline: 1.6746x; 1.0608x over previous
#include <cuda_runtime.h>
#include <cuda_bf16.h>
#include <math.h>
#include <stdint.h>

// ---------------------------------------------------------------------------
// BitNetV3 MLP via IMMA (mma.sync.m16n8k32.s8) tensor cores.
// out = BitLinear(silu(BitLinear(x,Wg)) * BitLinear(x,Wu), Wd)
// BitLinear(x,W): xq = int8-quant(FWHT(x)); wq = ternary int8; s32 GEMM; dequant.
// T=4096 tokens, H=2048, I=8192. Integer GEMM math is bit-exact.
// ---------------------------------------------------------------------------

#define T_TOK 4096
#define H_DIM 2048
#define I_DIM 8192

#define NORM_2048 0.022097086912079608f   // 1/sqrt(2048)
#define NORM_8192 0.011048543456039804f   // 1/sqrt(8192)

// ------------------------- scratch (allocation-free) -----------------------
__device__ __align__(16) int    g_qx1[T_TOK * H_DIM / 4];            //  8 MB
__device__ __align__(16) int    g_qx2[T_TOK * I_DIM / 4];            // 32 MB
__device__ float  g_as1[T_TOK];
__device__ float  g_as2[T_TOK];
__device__ __align__(16) int    g_qwg[I_DIM * H_DIM / 4];            // 16 MB
__device__ __align__(16) int    g_qwu[I_DIM * H_DIM / 4];            // 16 MB
__device__ __align__(16) int    g_qwd[H_DIM * I_DIM / 4];            // 16 MB
__device__ float  g_ws[4];
__device__ float  g_part[3 * 512];
__device__ float  g_gate[(size_t)T_TOK * I_DIM];                     // 128 MB

// ----------------------------- PTX helpers ---------------------------------
__device__ __forceinline__ uint32_t s2u(const void* p) {
    uint32_t a;
    asm("{ .reg .u64 t; cvta.to.shared.u64 t, %1; cvt.u32.u64 %0, t; }"
        : "=r"(a) : "l"(p));
    return a;
}
__device__ __forceinline__ void cp16(uint32_t d, const void* s) {
    asm volatile("cp.async.cg.shared.global [%0], [%1], 16;" :: "r"(d), "l"(s));
}
__device__ __forceinline__ void cp_commit() { asm volatile("cp.async.commit_group;"); }
__device__ __forceinline__ void cp_wait1()  { asm volatile("cp.async.wait_group 1;"); }

__device__ __forceinline__ void ldm_x4(uint32_t* r, uint32_t addr) {
    asm volatile("ldmatrix.sync.aligned.m8n8.x4.shared.b16 {%0,%1,%2,%3}, [%4];"
                 : "=r"(r[0]), "=r"(r[1]), "=r"(r[2]), "=r"(r[3]) : "r"(addr));
}
__device__ __forceinline__ void mma_s8(int* d, const uint32_t* a,
                                       uint32_t b0, uint32_t b1) {
    asm volatile(
        "mma.sync.aligned.m16n8k32.row.col.s32.s8.s8.s32 "
        "{%0,%1,%2,%3}, {%4,%5,%6,%7}, {%8,%9}, {%0,%1,%2,%3};"
        : "+r"(d[0]), "+r"(d[1]), "+r"(d[2]), "+r"(d[3])
        : "r"(a[0]), "r"(a[1]), "r"(a[2]), "r"(a[3]), "r"(b0), "r"(b1));
}

// --------------- batched weight prep (3 weights in 3 launches) -------------
__global__ void abs_sum_all(const float4* __restrict__ w0,
                            const float4* __restrict__ w1,
                            const float4* __restrict__ w2,
                            int n4, float* __restrict__ part) {
    const float4* w = (blockIdx.y == 0) ? w0 : (blockIdx.y == 1) ? w1 : w2;
    float s0 = 0.f, s1 = 0.f, s2 = 0.f, s3 = 0.f;
    int i = blockIdx.x * 256 + threadIdx.x;
    const int stride = 512 * 256;
    for (; i + 3 * stride < n4; i += 4 * stride) {
        float4 a = w[i];
        float4 b = w[i + stride];
        float4 c = w[i + 2 * stride];
        float4 d = w[i + 3 * stride];
        s0 += fabsf(a.x) + fabsf(a.y) + fabsf(a.z) + fabsf(a.w);
        s1 += fabsf(b.x) + fabsf(b.y) + fabsf(b.z) + fabsf(b.w);
        s2 += fabsf(c.x) + fabsf(c.y) + fabsf(c.z) + fabsf(c.w);
        s3 += fabsf(d.x) + fabsf(d.y) + fabsf(d.z) + fabsf(d.w);
    }
    for (; i < n4; i += stride) {
        float4 a = w[i];
        s0 += fabsf(a.x) + fabsf(a.y) + fabsf(a.z) + fabsf(a.w);
    }
    __shared__ float red[256];
    red[threadIdx.x] = (s0 + s1) + (s2 + s3);
    __syncthreads();
    for (int off = 128; off > 0; off >>= 1) {
        if ((int)threadIdx.x < off) red[threadIdx.x] += red[threadIdx.x + off];
        __syncthreads();
    }
    if (threadIdx.x == 0) part[blockIdx.y * 512 + blockIdx.x] = red[0];
}

__global__ void abs_final_all(const float* __restrict__ part, long long n,
                              float* __restrict__ ws) {
    __shared__ double red[256];
    double s = 0.0;
    for (int i = threadIdx.x; i < 512; i += 256)
        s += (double)part[blockIdx.x * 512 + i];
    red[threadIdx.x] = s;
    __syncthreads();
    for (int off = 128; off > 0; off >>= 1) {
        if ((int)threadIdx.x < off) red[threadIdx.x] += red[threadIdx.x + off];
        __syncthreads();
    }
    if (threadIdx.x == 0)
        ws[blockIdx.x] = fmaxf((float)(red[0] / (double)n), 1e-5f);
}

__global__ void quant_pack_all(const float* __restrict__ w0,
                               const float* __restrict__ w1,
                               const float* __restrict__ w2,
                               const float* __restrict__ sc,
                               int* __restrict__ q0, int* __restrict__ q1,
                               int* __restrict__ q2, int n4) {
    int i = blockIdx.x * 256 + threadIdx.x;
    if (i >= n4) return;
    const int which = blockIdx.y;
    const float* w = (which == 0) ? w0 : (which == 1) ? w1 : w2;
    int* q = (which == 0) ? q0 : (which == 1) ? q1 : q2;
    float s = sc[which];
    float4 v = reinterpret_cast<const float4*>(w)[i];
    int a = (int)fminf(fmaxf(rintf(v.x / s), -1.f), 1.f);
    int b = (int)fminf(fmaxf(rintf(v.y / s), -1.f), 1.f);
    int c = (int)fminf(fmaxf(rintf(v.z / s), -1.f), 1.f);
    int d = (int)fminf(fmaxf(rintf(v.w / s), -1.f), 1.f);
    q[i] = (a & 0xFF) | ((b & 0xFF) << 8) | ((c & 0xFF) << 16) | ((d & 0xFF) << 24);
}

// --------------- FWHT (last axis) + per-token int8 quant + pack ------------
template <int N, int TPB>
__global__ void fwht_quant(const float* __restrict__ X, int* __restrict__ Q,
                           float* __restrict__ scales, float norm) {
    __shared__ float s[N];
    __shared__ float red[TPB];
    const int t = blockIdx.x;
    const float* x = X + (size_t)t * N;

    for (int i = threadIdx.x; i < N; i += TPB) s[i] = x[i];
    __syncthreads();

    for (int h = 1; h < N; h <<= 1) {
        for (int p = threadIdx.x; p < N / 2; p += TPB) {
            int i = ((p & ~(h - 1)) << 1) | (p & (h - 1));
            float a = s[i], b = s[i + h];
            s[i] = a + b;
            s[i + h] = a - b;
        }
        __syncthreads();
    }

    float m = 0.f;
    for (int i = threadIdx.x; i < N; i += TPB)
        m = fmaxf(m, fabsf(s[i] * norm));
    red[threadIdx.x] = m;
    __syncthreads();
    for (int off = TPB / 2; off > 0; off >>= 1) {
        if ((int)threadIdx.x < off)
            red[threadIdx.x] = fmaxf(red[threadIdx.x], red[threadIdx.x + off]);
        __syncthreads();
    }
    float scale = 127.f / fmaxf(red[0], 1e-5f);
    if (threadIdx.x == 0) scales[t] = scale;

    for (int i = threadIdx.x; i < N / 4; i += TPB) {
        float v0 = s[4 * i + 0] * norm * scale;
        float v1 = s[4 * i + 1] * norm * scale;
        float v2 = s[4 * i + 2] * norm * scale;
        float v3 = s[4 * i + 3] * norm * scale;
        int q0 = (int)fminf(fmaxf(rintf(v0), -128.f), 127.f);
        int q1 = (int)fminf(fmaxf(rintf(v1), -128.f), 127.f);
        int q2 = (int)fminf(fmaxf(rintf(v2), -128.f), 127.f);
        int q3 = (int)fminf(fmaxf(rintf(v3), -128.f), 127.f);
        Q[(size_t)t * (N / 4) + i] = (q0 & 0xFF) | ((q1 & 0xFF) << 8)
                                   | ((q2 & 0xFF) << 16) | ((q3 & 0xFF) << 24);
    }
}

// ---------------------------- IMMA int8 GEMM -------------------------------
// CTA: 128x128 tile, 8 warps (4M x 2N), warp tile 32x64.
// K in 128-byte SW128 SMEM chunks, 3-stage ring / prefetch distance 1,
// ONE __syncthreads per chunk placed AFTER cp.async.wait_group (both publishes
// all threads' chunk-c data and fences compute(c-1) before stage reuse).
// C[t,o] = acc * wS / actScale[t]. MODE 1: C holds gate; write silu(gate)*up.
#define STAGE_BYTES 32768
#define GEMM_SMEM   (3 * STAGE_BYTES)

template <int MODE>
__global__ __launch_bounds__(256, 2)
void gemm_imma(const char* __restrict__ A,   // [M_total][K] int8 row-major
               const char* __restrict__ Bw,  // [O][K]      int8 row-major
               float* __restrict__ C,        // [M_total][O] f32
               int O, int K,
               const float* __restrict__ actScale,
               const float* __restrict__ wScale) {
    extern __shared__ __align__(1024) char smem[];
    const uint32_t S0 = s2u(smem);   // stage s: A at S0+s*32768, B at +16384

    const int tid = threadIdx.x;
    const int lane = tid & 31, w = tid >> 5;
    const int wm = w >> 1, wn = w & 1;       // warp grid 4(M) x 2(N)
    const int blockM = blockIdx.y * 128, blockN = blockIdx.x * 128;

    // ldmatrix lane geometry (SW128: addr = row*128 + (k ^ ((row&7)<<4)))
    const int aRow = wm * 32 + (lane & 7) + ((lane >> 3) & 1) * 8;
    const uint32_t aKh = ((lane >> 4) & 1) * 16;
    const uint32_t aQ  = (uint32_t)(aRow & 7) << 4;
    const int bRow = wn * 64 + (lane & 7) + ((lane >> 4) & 1) * 8;
    const uint32_t bKh = ((lane >> 3) & 1) * 16;
    const uint32_t bQ  = (uint32_t)(bRow & 7) << 4;

    int acc[2][8][4];
#pragma unroll
    for (int i = 0; i < 2; i++)
#pragma unroll
        for (int j = 0; j < 8; j++)
#pragma unroll
            for (int k = 0; k < 4; k++) acc[i][j][k] = 0;

    const char* gA = A  + (size_t)blockM * K;
    const char* gB = Bw + (size_t)blockN * K;
    const int nC = K >> 7;

    // loader: 1024 16B segments per matrix, 256 threads -> 4 each
#define LOAD_CHUNK(stage, kt)                                                 \
    do {                                                                      \
        const uint32_t dA = S0 + (stage) * STAGE_BYTES;                       \
        const uint32_t dB = dA + 16384;                                       \
        _Pragma("unroll")                                                     \
        for (int i = 0; i < 4; i++) {                                         \
            int g = i * 256 + tid;                                            \
            uint32_t off = (uint32_t)g * 16;                                  \
            uint32_t sw = off ^ ((off >> 3) & 0x70);                          \
            int row = g >> 3, cc = (g & 7) * 16;                              \
            cp16(dA + sw, gA + (size_t)row * K + (kt) + cc);                  \
            cp16(dB + sw, gB + (size_t)row * K + (kt) + cc);                  \
        }                                                                     \
        cp_commit();                                                          \
    } while (0)

    LOAD_CHUNK(0, 0);

    int st = 0;
    for (int c = 0; c < nC; c++) {
        if (c + 1 < nC) {
            int ns = st + 1; if (ns == 3) ns = 0;
            LOAD_CHUNK(ns, (c + 1) << 7);
        } else {
            cp_commit();                 // empty group: keep wait counting uniform
        }
        cp_wait1();                      // this thread's chunk-c copies done
        __syncthreads();                 // publish ALL threads' chunk-c data

        const uint32_t aBase = S0 + st * STAGE_BYTES + (uint32_t)aRow * 128;
        const uint32_t bBase = S0 + st * STAGE_BYTES + 16384 + (uint32_t)bRow * 128;
#pragma unroll
        for (int ks = 0; ks < 4; ks++) {
            uint32_t Af[2][4], Bf[4][4];
#pragma unroll
            for (int mr = 0; mr < 2; mr++)
                ldm_x4(Af[mr], aBase + mr * (16 * 128)
                               + (((uint32_t)(ks * 32) + aKh) ^ aQ));
#pragma unroll
            for (int ng = 0; ng < 4; ng++)
                ldm_x4(Bf[ng], bBase + ng * (16 * 128)
                               + (((uint32_t)(ks * 32) + bKh) ^ bQ));
#pragma unroll
            for (int mr = 0; mr < 2; mr++)
#pragma unroll
                for (int nb = 0; nb < 8; nb++)
                    mma_s8(acc[mr][nb], Af[mr],
                           Bf[nb >> 1][(nb & 1) * 2],
                           Bf[nb >> 1][(nb & 1) * 2 + 1]);
        }
        if (++st == 3) st = 0;
    }
#undef LOAD_CHUNK

    // ---------------- epilogue: dequant + store (from registers) -----------
    const float wS = wScale[0];
    const int r = lane >> 2, cq = (lane & 3) * 2;
#pragma unroll
    for (int mr = 0; mr < 2; mr++) {
#pragma unroll
        for (int half = 0; half < 2; half++) {
            const int m = blockM + wm * 32 + mr * 16 + half * 8 + r;
            const float f = wS / __ldg(&actScale[m]);
            float* crow = C + (size_t)m * O + blockN + wn * 64;
#pragma unroll
            for (int nb = 0; nb < 8; nb++) {
                float2 v;
                v.x = (float)acc[mr][nb][half * 2]     * f;
                v.y = (float)acc[mr][nb][half * 2 + 1] * f;
                float* p = crow + nb * 8 + cq;
                if (MODE == 1) {
                    float2 g = *reinterpret_cast<const float2*>(p);
                    v.x *= g.x / (1.f + expf(-g.x));
                    v.y *= g.y / (1.f + expf(-g.y));
                }
                *reinterpret_cast<float2*>(p) = v;
            }
        }
    }
}

// ------------------------------- launcher ----------------------------------
extern "C" void kernel_launch(void* const* d_in, const int* in_sizes, int n_in,
                              void* d_out, int out_size) {
    const float* x  = (const float*)d_in[0];
    const float* wg = (const float*)d_in[1];
    const float* wu = (const float*)d_in[2];
    const float* wd = (const float*)d_in[3];
    float* out = (float*)d_out;

    void* p;
    cudaGetSymbolAddress(&p, g_qx1);  int*   qx1  = (int*)p;
    cudaGetSymbolAddress(&p, g_qx2);  int*   qx2  = (int*)p;
    cudaGetSymbolAddress(&p, g_as1);  float* as1  = (float*)p;
    cudaGetSymbolAddress(&p, g_as2);  float* as2  = (float*)p;
    cudaGetSymbolAddress(&p, g_qwg);  int*   qwg  = (int*)p;
    cudaGetSymbolAddress(&p, g_qwu);  int*   qwu  = (int*)p;
    cudaGetSymbolAddress(&p, g_qwd);  int*   qwd  = (int*)p;
    cudaGetSymbolAddress(&p, g_ws);   float* ws   = (float*)p;
    cudaGetSymbolAddress(&p, g_part); float* part = (float*)p;
    cudaGetSymbolAddress(&p, g_gate); float* gate = (float*)p;

    cudaFuncSetAttribute(gemm_imma<0>, cudaFuncAttributeMaxDynamicSharedMemorySize, GEMM_SMEM);
    cudaFuncSetAttribute(gemm_imma<1>, cudaFuncAttributeMaxDynamicSharedMemorySize, GEMM_SMEM);

    const long long nW = (long long)I_DIM * H_DIM;
    const int n4 = (int)(nW / 4);

    // launches 0-2: weight scales + ternary pack (all three weights batched)
    abs_sum_all<<<dim3(512, 3), 256>>>((const float4*)wg, (const float4*)wu,
                                       (const float4*)wd, n4, part);
    abs_final_all<<<3, 256>>>(part, nW, ws);
    quant_pack_all<<<dim3((n4 + 255) / 256, 3), 256>>>(wg, wu, wd, ws,
                                                       qwg, qwu, qwd, n4);

    // launch 3: FWHT(2048) + int8 quant of input (shared by gate & up)
    fwht_quant<H_DIM, 256><<<T_TOK, 256>>>(x, qx1, as1, NORM_2048);

    // launches 4-5: gate = xq@Wg^T, then h = silu(gate)*(xq@Wu^T) fused
    gemm_imma<0><<<dim3(I_DIM / 128, T_TOK / 128), 256, GEMM_SMEM>>>(
        (const char*)qx1, (const char*)qwg, gate, I_DIM, H_DIM, as1, ws + 0);
    gemm_imma<1><<<dim3(I_DIM / 128, T_TOK / 128), 256, GEMM_SMEM>>>(
        (const char*)qx1, (const char*)qwu, gate, I_DIM, H_DIM, as1, ws + 1);

    // launch 6: FWHT(8192) + int8 quant of h
    fwht_quant<I_DIM, 512><<<T_TOK, 512>>>(gate, qx2, as2, NORM_8192);

    // launch 7: out = hq @ Wd^T
    gemm_imma<0><<<dim3(H_DIM / 128, T_TOK / 128), 256, GEMM_SMEM>>>(
        (const char*)qx2, (const char*)qwd, out, H_DIM, I_DIM, as2, ws + 2);
}